// round 4
// baseline (speedup 1.0000x reference)
#include <cuda_runtime.h>

// Problem constants (static in the reference: SIZES[g] = 256 + 16*g, B=16)
#define NB 16
#define IN_DIM 16
#define HID 64
#define OUTD 32
#define N_TOT 6016
#define N_PAIRS 2349056

// t scratch: per-node MLP output [N_TOT, 32] = 770 KB
__device__ float g_t[N_TOT * OUTD];

// starts[g] = sum_{h<g} sizes[h]; starts[16] = 6016 (sentinel)
__constant__ int c_starts[NB + 1] = {
    0, 256, 528, 816, 1120, 1440, 1776, 2128,
    2496, 2880, 3280, 3696, 4128, 4576, 5040, 5520, 6016};
__constant__ int c_sizes[NB] = {
    256, 272, 288, 304, 320, 336, 352, 368,
    384, 400, 416, 432, 448, 464, 480, 496};
// pair_cum[g] = sum_{h<g} sizes[h]^2
__constant__ int c_paircum[NB] = {
    0, 65536, 139520, 222464, 314880, 417280, 530176, 654080,
    789504, 936960, 1096960, 1270016, 1456640, 1657344, 1872640, 2103040};

// ---------------------------------------------------------------------------
// Kernel 1: per-node MLP  t[n] = relu(ape[n] @ W1 + b1) @ W2 + b2
// 8 threads per node (one per output quad). 256-thread block = 32 nodes.
// Phase 1: each thread computes 8 hidden values (h = part + 8*hh) -> shared.
// Phase 2: each thread accumulates its 4 outputs over all 64 hidden values.
// Per-thread FMA ~384 (vs 3072 in the thread-per-node version); grid 188 blocks.
// ---------------------------------------------------------------------------
#define NPB 32           // nodes per block (6016 = 188 * 32 exactly)
#define HPAD 65          // hidden smem stride (conflict-free phase-2 reads)

__global__ __launch_bounds__(256) void mlp_kernel(
    const float* __restrict__ ape, const float* __restrict__ W1,
    const float* __restrict__ b1, const float* __restrict__ W2,
    const float* __restrict__ b2)
{
    __shared__ float sW1[IN_DIM * HID];    // [k][h], 4 KB
    __shared__ float sW2[HID * OUTD];      // [h][o], 8 KB
    __shared__ float sb1[HID];
    __shared__ float sb2[OUTD];
    __shared__ float sh[NPB * HPAD];       // hidden, padded

    const int tid = threadIdx.x;
    for (int i = tid; i < IN_DIM * HID; i += 256) sW1[i] = W1[i];
    for (int i = tid; i < HID * OUTD; i += 256) sW2[i] = W2[i];
    if (tid < HID)  sb1[tid] = b1[tid];
    if (tid < OUTD) sb2[tid] = b2[tid];
    __syncthreads();

    const int local = tid >> 3;        // node within block (0..31)
    const int part  = tid & 7;         // quad / hidden-part index (0..7)
    const int n     = blockIdx.x * NPB + local;

    // load this node's 16 inputs (8 threads share the row -> L1 broadcast)
    float a[IN_DIM];
    const float4* ap = reinterpret_cast<const float4*>(ape + (size_t)n * IN_DIM);
#pragma unroll
    for (int k4 = 0; k4 < IN_DIM / 4; k4++) {
        float4 v = __ldg(ap + k4);
        a[k4 * 4 + 0] = v.x; a[k4 * 4 + 1] = v.y;
        a[k4 * 4 + 2] = v.z; a[k4 * 4 + 3] = v.w;
    }

    // phase 1: hidden values h = part + 8*hh  (parts hit distinct banks in sW1)
#pragma unroll
    for (int hh = 0; hh < 8; hh++) {
        const int h = part + 8 * hh;
        float v = sb1[h];
#pragma unroll
        for (int k = 0; k < IN_DIM; k++) v = fmaf(a[k], sW1[k * HID + h], v);
        sh[local * HPAD + h] = fmaxf(v, 0.0f);
    }
    __syncthreads();

    // phase 2: 4 outputs per thread (o = part*4 .. part*4+3)
    float acc0 = sb2[part * 4 + 0];
    float acc1 = sb2[part * 4 + 1];
    float acc2 = sb2[part * 4 + 2];
    float acc3 = sb2[part * 4 + 3];
#pragma unroll 8
    for (int h = 0; h < HID; h++) {
        const float hv = sh[local * HPAD + h];
        const float* w = sW2 + h * OUTD + part * 4;
        acc0 = fmaf(hv, w[0], acc0);
        acc1 = fmaf(hv, w[1], acc1);
        acc2 = fmaf(hv, w[2], acc2);
        acc3 = fmaf(hv, w[3], acc3);
    }

    *reinterpret_cast<float4*>(g_t + (size_t)n * OUTD + part * 4) =
        make_float4(acc0, acc1, acc2, acc3);
}

// ---------------------------------------------------------------------------
// Kernel 2: pairwise outer-sum, ragged gather order.
// Grid: one block per global node row (b, i). 256 threads = 32 j-lanes x 8 quads.
// Software-pipelined: prefetch t[j+32] before storing row j so stores never
// wait behind the next L2-hit load.
// ---------------------------------------------------------------------------
__global__ __launch_bounds__(256) void pair_kernel(float* __restrict__ out)
{
    const int row = blockIdx.x;

    int b = 0;
#pragma unroll
    for (int g = 1; g < NB; g++) b += (row >= c_starts[g]) ? 1 : 0;

    const int gbase = c_starts[b];
    const int nb    = c_sizes[b];
    const int i     = row - gbase;
    const int orow0 = c_paircum[b] + i * nb;   // first output row for this (b,i)

    const int q  = threadIdx.x & 7;    // quad index (q*4 .. q*4+3 of the 32 outs)
    const int jl = threadIdx.x >> 3;   // j lane (0..31)

    const float4 ti = *reinterpret_cast<const float4*>(g_t + (size_t)row * OUTD + q * 4);

    int j = jl;                        // jl < 32 <= nb always -> at least one trip
    float4 tj = __ldg(reinterpret_cast<const float4*>(
        g_t + (size_t)(gbase + j) * OUTD + q * 4));

    for (;;) {
        const int jn = j + 32;
        const bool more = jn < nb;
        float4 tn;
        if (more)
            tn = __ldg(reinterpret_cast<const float4*>(
                g_t + (size_t)(gbase + jn) * OUTD + q * 4));
        float4 r;
        r.x = ti.x + tj.x; r.y = ti.y + tj.y;
        r.z = ti.z + tj.z; r.w = ti.w + tj.w;
        __stcs(reinterpret_cast<float4*>(
                   out + (size_t)(orow0 + j) * OUTD + q * 4), r);
        if (!more) break;
        j = jn; tj = tn;
    }
}

extern "C" void kernel_launch(void* const* d_in, const int* in_sizes, int n_in,
                              void* d_out, int out_size)
{
    const float* ape = (const float*)d_in[0];
    const float* W1  = (const float*)d_in[1];
    const float* b1  = (const float*)d_in[2];
    const float* W2  = (const float*)d_in[3];
    const float* b2  = (const float*)d_in[4];
    float* out = (float*)d_out;

    mlp_kernel<<<N_TOT / NPB, 256>>>(ape, W1, b1, W2, b2);
    pair_kernel<<<N_TOT, 256>>>(out);
}